// round 1
// baseline (speedup 1.0000x reference)
#include <cuda_runtime.h>
#include <math.h>

#define H 64
#define HEADS 4
#define HID 64
#define RT 4
#define APT 3
#define N_AMB 1023
#define NN 1024
#define SLOPE 0.2f
#define NPB 8   // nodes per block in projection kernel

// ---- scratch (no allocation allowed; __device__ globals) ----
__device__ float d_hidden1[64];
__device__ float d_gr0[256];
__device__ float d_WlT[64 * 256];
__device__ float d_WrT[64 * 256];
__device__ float d_gr[NN * 256];     // 1 MB
__device__ float d_e[NN * 4];
__device__ float d_a[NN * 4];
__device__ float d_part[16 * 256];
__device__ float d_c0[64];

__device__ __forceinline__ float leaky(float x) { return x >= 0.f ? x : SLOPE * x; }

// ---------------------------------------------------------------------------
// K0: transpose W_l, W_r (256x64 -> 64x256) for coalesced reads in K2.
// ---------------------------------------------------------------------------
__global__ void k0_transpose(const float* __restrict__ Wl, const float* __restrict__ Wr) {
    for (int idx = threadIdx.x; idx < 256 * 64; idx += blockDim.x) {
        int o = idx >> 6, k = idx & 63;
        d_WlT[k * 256 + o] = Wl[idx];
        d_WrT[k * 256 + o] = Wr[idx];
    }
}

// ---------------------------------------------------------------------------
// K1: per-role-type routing chain -> hidden_1, plus g_r[0] = hidden_1 @ W_r^T
// One block, 64 threads. Work is tiny but strictly sequential over RT.
// ---------------------------------------------------------------------------
__global__ void k1_routing(const float* __restrict__ hidden, const float* __restrict__ ta,
                           const float* __restrict__ Wself, const float* __restrict__ bself,
                           const float* __restrict__ Wmerge, const float* __restrict__ bmerge,
                           const float* __restrict__ Wtrans, const float* __restrict__ btrans,
                           const float* __restrict__ Wr) {
    __shared__ float s_h1[64], s_avg[64], s_tmp[64], s_new[64];
    int t = threadIdx.x;  // 0..63
    float acc = bself[t];
    #pragma unroll 8
    for (int k = 0; k < 64; k++) acc += hidden[k] * Wself[t * 64 + k];
    s_h1[t] = acc;
    __syncthreads();
    for (int rt = 0; rt < RT; rt++) {
        // mean over the 3 agents (shape [RT,APT,1,H] flat: (rt*3+a)*64 + k)
        s_avg[t] = (ta[(rt * 3 + 0) * 64 + t] + ta[(rt * 3 + 1) * 64 + t] +
                    ta[(rt * 3 + 2) * 64 + t]) * (1.f / 3.f);
        __syncthreads();
        float tm = btrans[rt * 64 + t];
        #pragma unroll 8
        for (int k = 0; k < 64; k++) tm += s_avg[k] * Wtrans[rt * 4096 + t * 64 + k];
        s_tmp[t] = tm;
        __syncthreads();
        float m = bmerge[t];
        #pragma unroll 8
        for (int k = 0; k < 64; k++) m += s_h1[k] * Wmerge[t * 128 + k];
        #pragma unroll 8
        for (int k = 0; k < 64; k++) m += s_tmp[k] * Wmerge[t * 128 + 64 + k];
        s_new[t] = leaky(m);
        __syncthreads();
        s_h1[t] = s_new[t];
        __syncthreads();
    }
    d_hidden1[t] = s_h1[t];
    // g_r0[o] = sum_k hidden_1[k] * W_r[o,k]   (4 outputs per thread)
    #pragma unroll
    for (int q = 0; q < 4; q++) {
        int o = t + 64 * q;
        float g = 0.f;
        #pragma unroll 8
        for (int k = 0; k < 64; k++) g += s_h1[k] * Wr[o * 64 + k];
        d_gr0[o] = g;
    }
}

// ---------------------------------------------------------------------------
// K2: for all nodes j: g_l[j], g_r[j] (store g_r), and the attention row
//     e[0,j,h] = sum_f leaky(g_l[j,h,f] + g_r0[h,f]) * w_attn[f].
// 128 blocks x 256 threads; 8 nodes per block so each weight load feeds 16 FMAs.
// ---------------------------------------------------------------------------
__global__ void k2_gat_proj(const float* __restrict__ amb, const float* __restrict__ wattn) {
    __shared__ float s_h[NPB][64];
    __shared__ float s_wred[NPB][8];
    int tid = threadIdx.x;  // 0..255
    int base = blockIdx.x * NPB;
    #pragma unroll
    for (int p = 0; p < (NPB * 64) / 256; p++) {
        int idx = tid + p * 256;
        int r = idx >> 6, k = idx & 63;
        int j = base + r;
        s_h[r][k] = (j == 0) ? d_hidden1[k] : amb[(j - 1) * 64 + k];
    }
    __syncthreads();
    float al[NPB], ar[NPB];
    #pragma unroll
    for (int r = 0; r < NPB; r++) { al[r] = 0.f; ar[r] = 0.f; }
    #pragma unroll 4
    for (int k = 0; k < 64; k++) {
        float wl = d_WlT[k * 256 + tid];   // coalesced
        float wr = d_WrT[k * 256 + tid];
        #pragma unroll
        for (int r = 0; r < NPB; r++) {
            float hv = s_h[r][k];          // broadcast
            al[r] = fmaf(hv, wl, al[r]);
            ar[r] = fmaf(hv, wr, ar[r]);
        }
    }
    #pragma unroll
    for (int r = 0; r < NPB; r++) d_gr[(base + r) * 256 + tid] = ar[r];

    float g0 = d_gr0[tid];
    float wa = wattn[tid & 63];
    int lane = tid & 31, warp = tid >> 5;
    #pragma unroll
    for (int r = 0; r < NPB; r++) {
        float c = leaky(al[r] + g0) * wa;
        #pragma unroll
        for (int off = 16; off; off >>= 1) c += __shfl_down_sync(0xffffffffu, c, off);
        if (lane == 0) s_wred[r][warp] = c;
    }
    __syncthreads();
    if (tid < NPB * 4) {
        int r = tid >> 2, h = tid & 3;  // head h spans warps 2h, 2h+1
        d_e[(base + r) * 4 + h] = s_wred[r][2 * h] + s_wred[r][2 * h + 1];
    }
}

// ---------------------------------------------------------------------------
// K3a: softmax over j for each head: a[j,h] = exp(e-m)/Z.  1 block, 256 thr.
// ---------------------------------------------------------------------------
__global__ void k3a_softmax() {
    __shared__ float s_e[NN * 4];
    __shared__ float s_m[4], s_z[4];
    int tid = threadIdx.x;
    for (int i = tid; i < NN * 4; i += 256) s_e[i] = d_e[i];
    __syncthreads();
    int warp = tid >> 5, lane = tid & 31;
    if (warp < 4) {  // warp w owns head w
        float m = -1e30f;
        for (int j = lane; j < NN; j += 32) m = fmaxf(m, s_e[j * 4 + warp]);
        #pragma unroll
        for (int off = 16; off; off >>= 1) m = fmaxf(m, __shfl_xor_sync(0xffffffffu, m, off));
        float z = 0.f;
        for (int j = lane; j < NN; j += 32) z += __expf(s_e[j * 4 + warp] - m);
        #pragma unroll
        for (int off = 16; off; off >>= 1) z += __shfl_xor_sync(0xffffffffu, z, off);
        if (lane == 0) { s_m[warp] = m; s_z[warp] = 1.f / z; }
    }
    __syncthreads();
    for (int i = tid; i < NN * 4; i += 256) {
        int h = i & 3;
        d_a[i] = __expf(s_e[i] - s_m[h]) * s_z[h];
    }
}

// ---------------------------------------------------------------------------
// K3b: attn_res partials: block b sums j in [64b, 64b+64). 16 blocks x 256.
// Deterministic (fixed partial layout, no float atomics).
// ---------------------------------------------------------------------------
__global__ void k3b_attnres() {
    int tid = threadIdx.x;
    int h = tid >> 6;
    float acc = 0.f;
    int j0 = blockIdx.x * 64;
    #pragma unroll 4
    for (int jj = 0; jj < 64; jj++) {
        int j = j0 + jj;
        acc = fmaf(d_a[j * 4 + h], d_gr[j * 256 + tid], acc);
    }
    d_part[blockIdx.x * 256 + tid] = acc;
}

// ---------------------------------------------------------------------------
// K3c: combine partials -> hidden_2 (mean over heads), then fold the constant
// half of the MLP's concat input: c0[o] = bd0[o] + sum_k hidden_2[k]*Wd0[o,64+k]
// ---------------------------------------------------------------------------
__global__ void k3c_h2_c0(const float* __restrict__ Wd0, const float* __restrict__ bd0) {
    __shared__ float s_h2[64];
    int t = threadIdx.x;  // 64 threads
    float acc = 0.f;
    #pragma unroll
    for (int b = 0; b < 16; b++)
        #pragma unroll
        for (int h = 0; h < 4; h++)
            acc += d_part[b * 256 + h * 64 + t];
    s_h2[t] = 0.25f * acc;
    __syncthreads();
    float c = bd0[t];
    #pragma unroll 8
    for (int k = 0; k < 64; k++) c += s_h2[k] * Wd0[t * 128 + 64 + k];
    d_c0[t] = c;
}

// ---------------------------------------------------------------------------
// K4: type_define MLP over 1023 rows. One row per block, 128 threads,
// warp-cooperative dot products (lane-coalesced weight rows, shfl reduce).
// ---------------------------------------------------------------------------
__global__ void k4_mlp(const float* __restrict__ amb,
                       const float* __restrict__ Wd0,
                       const float* __restrict__ Wd1, const float* __restrict__ bd1,
                       const float* __restrict__ Wd2, const float* __restrict__ bd2,
                       float* __restrict__ out) {
    __shared__ float s_x[64], s_y0[64], s_y1[128];
    int tid = threadIdx.x, lane = tid & 31, warp = tid >> 5;
    int row = blockIdx.x;
    if (tid < 64) s_x[tid] = amb[row * 64 + tid];
    __syncthreads();
    // stage 1: 64 outputs; only the ambiguous half of the concat (rest is in c0)
    #pragma unroll
    for (int i = 0; i < 16; i++) {
        int o = warp * 16 + i;
        float p = s_x[lane] * Wd0[o * 128 + lane] + s_x[lane + 32] * Wd0[o * 128 + lane + 32];
        #pragma unroll
        for (int off = 16; off; off >>= 1) p += __shfl_down_sync(0xffffffffu, p, off);
        if (lane == 0) s_y0[o] = leaky(d_c0[o] + p);
    }
    __syncthreads();
    // stage 2: 128 outputs
    #pragma unroll
    for (int i = 0; i < 32; i++) {
        int o = warp * 32 + i;
        float p = s_y0[lane] * Wd1[o * 64 + lane] + s_y0[lane + 32] * Wd1[o * 64 + lane + 32];
        #pragma unroll
        for (int off = 16; off; off >>= 1) p += __shfl_down_sync(0xffffffffu, p, off);
        if (lane == 0) s_y1[o] = leaky(bd1[o] + p);
    }
    __syncthreads();
    // stage 3: 4 outputs, one per warp, + sigmoid
    {
        const float* w = Wd2 + warp * 128;
        float p = s_y1[lane] * w[lane] + s_y1[lane + 32] * w[lane + 32]
                + s_y1[lane + 64] * w[lane + 64] + s_y1[lane + 96] * w[lane + 96];
        #pragma unroll
        for (int off = 16; off; off >>= 1) p += __shfl_down_sync(0xffffffffu, p, off);
        if (lane == 0) out[row * 4 + warp] = 1.f / (1.f + __expf(-(bd2[warp] + p)));
    }
}

// ---------------------------------------------------------------------------
extern "C" void kernel_launch(void* const* d_in, const int* in_sizes, int n_in,
                              void* d_out, int out_size) {
    const float* hidden = (const float*)d_in[0];
    const float* amb    = (const float*)d_in[1];
    const float* ta     = (const float*)d_in[2];
    const float* Wself  = (const float*)d_in[3];
    const float* bself  = (const float*)d_in[4];
    const float* Wmerge = (const float*)d_in[5];
    const float* bmerge = (const float*)d_in[6];
    const float* Wtrans = (const float*)d_in[7];
    const float* btrans = (const float*)d_in[8];
    const float* Wl     = (const float*)d_in[9];
    const float* Wr     = (const float*)d_in[10];
    const float* wattn  = (const float*)d_in[11];
    const float* Wd0    = (const float*)d_in[12];
    const float* bd0    = (const float*)d_in[13];
    const float* Wd1    = (const float*)d_in[14];
    const float* bd1    = (const float*)d_in[15];
    const float* Wd2    = (const float*)d_in[16];
    const float* bd2    = (const float*)d_in[17];
    float* out = (float*)d_out;

    k0_transpose<<<1, 256>>>(Wl, Wr);
    k1_routing<<<1, 64>>>(hidden, ta, Wself, bself, Wmerge, bmerge, Wtrans, btrans, Wr);
    k2_gat_proj<<<NN / NPB, 256>>>(amb, wattn);
    k3a_softmax<<<1, 256>>>();
    k3b_attnres<<<16, 256>>>();
    k3c_h2_c0<<<1, 64>>>(Wd0, bd0);
    k4_mlp<<<N_AMB, 128>>>(amb, Wd0, Wd1, bd1, Wd2, bd2, out);
}

// round 2
// speedup vs baseline: 2.4576x; 2.4576x over previous
#include <cuda_runtime.h>
#include <math.h>

#define RT 4
#define N_AMB 1023
#define NN 1024
#define SLOPE 0.2f
#define NPB 8
#define NBLK (NN / NPB)   // 128

// ---- scratch (__device__ globals; no allocation allowed) ----
__device__ float d_hidden1[64];
__device__ float d_gr0[256];
__device__ float d_WlT[64 * 256];
__device__ float d_WrT[64 * 256];
__device__ float d_pm[NBLK * 4];
__device__ float d_pz[NBLK * 4];
__device__ float d_pacc[NBLK * 256];
__device__ float d_c0[64];

__device__ __forceinline__ float leaky(float x) { return x >= 0.f ? x : SLOPE * x; }

__device__ __forceinline__ float red4(float v) {
    v += __shfl_xor_sync(0xffffffffu, v, 1, 4);
    v += __shfl_xor_sync(0xffffffffu, v, 2, 4);
    return v;
}

// ---------------------------------------------------------------------------
// KA: 3 independent blocks.
//   block 0/1: transpose W_l / W_r (256x64 -> 64x256) for coalesced KB reads.
//   block 2:   routing chain -> hidden_1, g_r0.  4 threads per dot, float4
//              loads -> 4x shorter latency chain than 1-thread-per-row.
// ---------------------------------------------------------------------------
__global__ void kA(const float* __restrict__ hidden, const float* __restrict__ ta,
                   const float* __restrict__ Wself, const float* __restrict__ bself,
                   const float* __restrict__ Wmerge, const float* __restrict__ bmerge,
                   const float* __restrict__ Wtrans, const float* __restrict__ btrans,
                   const float* __restrict__ Wl, const float* __restrict__ Wr) {
    int tid = threadIdx.x;
    if (blockIdx.x == 0) {
        for (int idx = tid; idx < 256 * 64; idx += 256) {
            int o = idx >> 6, k = idx & 63;
            d_WlT[k * 256 + o] = Wl[idx];
        }
        return;
    }
    if (blockIdx.x == 1) {
        for (int idx = tid; idx < 256 * 64; idx += 256) {
            int o = idx >> 6, k = idx & 63;
            d_WrT[k * 256 + o] = Wr[idx];
        }
        return;
    }
    // ---- routing (block 2) ----
    __shared__ float s_cat[128];   // [h1 | tmp]
    __shared__ float s_in[64];
    __shared__ float s_m[64];
    int o = tid >> 2, q = tid & 3;
    if (tid < 64) s_in[tid] = hidden[tid];
    __syncthreads();
    {   // hidden_1 = hidden @ W_self^T + b_self
        float s = 0.f;
        const float4* w4 = (const float4*)(Wself + o * 64 + q * 16);
        #pragma unroll
        for (int i = 0; i < 4; i++) {
            float4 w = w4[i];
            int k = q * 16 + i * 4;
            s += w.x * s_in[k] + w.y * s_in[k + 1] + w.z * s_in[k + 2] + w.w * s_in[k + 3];
        }
        s = red4(s);
        if (q == 0) s_cat[o] = bself[o] + s;
    }
    __syncthreads();
    for (int rt = 0; rt < RT; rt++) {
        if (tid < 64)
            s_in[tid] = (ta[(rt * 3 + 0) * 64 + tid] + ta[(rt * 3 + 1) * 64 + tid] +
                         ta[(rt * 3 + 2) * 64 + tid]) * (1.f / 3.f);
        __syncthreads();
        {   // tmp = mean-agent @ W_trans[rt]^T + b_trans[rt]
            float s = 0.f;
            const float4* w4 = (const float4*)(Wtrans + rt * 4096 + o * 64 + q * 16);
            #pragma unroll
            for (int i = 0; i < 4; i++) {
                float4 w = w4[i];
                int k = q * 16 + i * 4;
                s += w.x * s_in[k] + w.y * s_in[k + 1] + w.z * s_in[k + 2] + w.w * s_in[k + 3];
            }
            s = red4(s);
            if (q == 0) s_cat[64 + o] = btrans[rt * 64 + o] + s;
        }
        __syncthreads();
        {   // merge over concat[h1, tmp]
            float s = 0.f;
            const float4* w4 = (const float4*)(Wmerge + o * 128 + q * 32);
            #pragma unroll
            for (int i = 0; i < 8; i++) {
                float4 w = w4[i];
                int k = q * 32 + i * 4;
                s += w.x * s_cat[k] + w.y * s_cat[k + 1] + w.z * s_cat[k + 2] + w.w * s_cat[k + 3];
            }
            s = red4(s);
            if (q == 0) s_m[o] = leaky(bmerge[o] + s);
        }
        __syncthreads();
        if (tid < 64) s_cat[tid] = s_m[tid];
        __syncthreads();
    }
    if (tid < 64) d_hidden1[tid] = s_cat[tid];
    {   // g_r0[o] = hidden_1 . W_r[o,:]  (one output per thread, float4)
        float g = 0.f;
        const float4* w4 = (const float4*)(Wr + tid * 64);
        #pragma unroll
        for (int i = 0; i < 16; i++) {
            float4 w = w4[i];
            int k = i * 4;
            g += w.x * s_cat[k] + w.y * s_cat[k + 1] + w.z * s_cat[k + 2] + w.w * s_cat[k + 3];
        }
        d_gr0[tid] = g;
    }
}

// ---------------------------------------------------------------------------
// KB: per block (8 nodes): g_l, g_r projections, attention-row logits e, and
// ONLINE-SOFTMAX partial (m, Z, weighted sum of g_r). g_r never leaves regs.
// ---------------------------------------------------------------------------
__global__ void kB(const float* __restrict__ amb, const float* __restrict__ wattn) {
    __shared__ float s_h[NPB][64];
    __shared__ float s_wred[NPB][8];
    __shared__ float s_e[NPB][4];
    int tid = threadIdx.x;
    int base = blockIdx.x * NPB;
    #pragma unroll
    for (int p = 0; p < 2; p++) {
        int idx = tid + p * 256;
        int r = idx >> 6, k = idx & 63;
        int j = base + r;
        s_h[r][k] = (j == 0) ? d_hidden1[k] : amb[(j - 1) * 64 + k];
    }
    __syncthreads();
    float al[NPB], ar[NPB];
    #pragma unroll
    for (int r = 0; r < NPB; r++) { al[r] = 0.f; ar[r] = 0.f; }
    #pragma unroll 4
    for (int k = 0; k < 64; k++) {
        float wl = d_WlT[k * 256 + tid];   // coalesced
        float wr = d_WrT[k * 256 + tid];
        #pragma unroll
        for (int r = 0; r < NPB; r++) {
            float hv = s_h[r][k];          // smem broadcast
            al[r] = fmaf(hv, wl, al[r]);
            ar[r] = fmaf(hv, wr, ar[r]);
        }
    }
    float g0 = d_gr0[tid];
    float wa = wattn[tid & 63];
    int lane = tid & 31, warp = tid >> 5;
    #pragma unroll
    for (int r = 0; r < NPB; r++) {
        float c = leaky(al[r] + g0) * wa;
        #pragma unroll
        for (int off = 16; off; off >>= 1) c += __shfl_down_sync(0xffffffffu, c, off);
        if (lane == 0) s_wred[r][warp] = c;
    }
    __syncthreads();
    if (tid < NPB * 4) {
        int r = tid >> 2, h = tid & 3;     // head h spans warps 2h, 2h+1
        s_e[r][h] = s_wred[r][2 * h] + s_wred[r][2 * h + 1];
    }
    __syncthreads();
    int h = tid >> 6;
    float m = -1e30f;
    #pragma unroll
    for (int r = 0; r < NPB; r++) m = fmaxf(m, s_e[r][h]);
    float z = 0.f, acc = 0.f;
    #pragma unroll
    for (int r = 0; r < NPB; r++) {
        float w = __expf(s_e[r][h] - m);
        z += w;
        acc = fmaf(w, ar[r], acc);
    }
    d_pacc[blockIdx.x * 256 + tid] = acc;
    if ((tid & 63) == 0) {
        d_pm[blockIdx.x * 4 + h] = m;
        d_pz[blockIdx.x * 4 + h] = z;
    }
}

// ---------------------------------------------------------------------------
// KC: combine 128 online-softmax partials (deterministic fixed order) ->
// hidden_2 (mean over heads) -> fold into MLP constant c0.
// ---------------------------------------------------------------------------
__global__ void kC(const float* __restrict__ Wd0, const float* __restrict__ bd0) {
    __shared__ float s_pm[512], s_pz[512], s_scale[512];
    __shared__ float s_M[4], s_Zinv[4];
    __shared__ float s_res[256], s_h2[64];
    int tid = threadIdx.x, lane = tid & 31, warp = tid >> 5;
    for (int i = tid; i < 512; i += 256) { s_pm[i] = d_pm[i]; s_pz[i] = d_pz[i]; }
    __syncthreads();
    if (warp < 4) {
        float m = -1e30f;
        for (int b = lane; b < NBLK; b += 32) m = fmaxf(m, s_pm[b * 4 + warp]);
        #pragma unroll
        for (int off = 16; off; off >>= 1) m = fmaxf(m, __shfl_xor_sync(0xffffffffu, m, off));
        if (lane == 0) s_M[warp] = m;
    }
    __syncthreads();
    for (int i = tid; i < 512; i += 256) s_scale[i] = __expf(s_pm[i] - s_M[i & 3]);
    __syncthreads();
    if (warp < 4) {
        float z = 0.f;
        for (int b = lane; b < NBLK; b += 32) z += s_pz[b * 4 + warp] * s_scale[b * 4 + warp];
        #pragma unroll
        for (int off = 16; off; off >>= 1) z += __shfl_xor_sync(0xffffffffu, z, off);
        if (lane == 0) s_Zinv[warp] = 1.f / z;
    }
    __syncthreads();
    int h = tid >> 6;
    float acc = 0.f;
    #pragma unroll 8
    for (int b = 0; b < NBLK; b++) acc = fmaf(d_pacc[b * 256 + tid], s_scale[b * 4 + h], acc);
    s_res[tid] = acc * s_Zinv[h];
    __syncthreads();
    if (tid < 64)
        s_h2[tid] = 0.25f * (s_res[tid] + s_res[64 + tid] + s_res[128 + tid] + s_res[192 + tid]);
    __syncthreads();
    #pragma unroll
    for (int i = 0; i < 8; i++) {   // c0: 8 warps x 8 outputs
        int o = warp * 8 + i;
        float p = s_h2[lane] * Wd0[o * 128 + 64 + lane] + s_h2[lane + 32] * Wd0[o * 128 + 96 + lane];
        #pragma unroll
        for (int off = 16; off; off >>= 1) p += __shfl_down_sync(0xffffffffu, p, off);
        if (lane == 0) d_c0[o] = bd0[o] + p;
    }
}

// ---------------------------------------------------------------------------
// KD: type_define MLP over 1023 rows. One row per block, 128 threads,
// warp-cooperative dot products.
// ---------------------------------------------------------------------------
__global__ void kD(const float* __restrict__ amb,
                   const float* __restrict__ Wd0,
                   const float* __restrict__ Wd1, const float* __restrict__ bd1,
                   const float* __restrict__ Wd2, const float* __restrict__ bd2,
                   float* __restrict__ out) {
    __shared__ float s_x[64], s_y0[64], s_y1[128];
    int tid = threadIdx.x, lane = tid & 31, warp = tid >> 5;
    int row = blockIdx.x;
    if (tid < 64) s_x[tid] = amb[row * 64 + tid];
    __syncthreads();
    #pragma unroll
    for (int i = 0; i < 16; i++) {      // stage 1 (64 out), c0 holds the const half
        int o = warp * 16 + i;
        float p = s_x[lane] * Wd0[o * 128 + lane] + s_x[lane + 32] * Wd0[o * 128 + lane + 32];
        #pragma unroll
        for (int off = 16; off; off >>= 1) p += __shfl_down_sync(0xffffffffu, p, off);
        if (lane == 0) s_y0[o] = leaky(d_c0[o] + p);
    }
    __syncthreads();
    #pragma unroll
    for (int i = 0; i < 32; i++) {      // stage 2 (128 out)
        int o = warp * 32 + i;
        float p = s_y0[lane] * Wd1[o * 64 + lane] + s_y0[lane + 32] * Wd1[o * 64 + lane + 32];
        #pragma unroll
        for (int off = 16; off; off >>= 1) p += __shfl_down_sync(0xffffffffu, p, off);
        if (lane == 0) s_y1[o] = leaky(bd1[o] + p);
    }
    __syncthreads();
    {                                    // stage 3 (4 out) + sigmoid
        const float* w = Wd2 + warp * 128;
        float p = s_y1[lane] * w[lane] + s_y1[lane + 32] * w[lane + 32]
                + s_y1[lane + 64] * w[lane + 64] + s_y1[lane + 96] * w[lane + 96];
        #pragma unroll
        for (int off = 16; off; off >>= 1) p += __shfl_down_sync(0xffffffffu, p, off);
        if (lane == 0) out[row * 4 + warp] = 1.f / (1.f + __expf(-(bd2[warp] + p)));
    }
}

// ---------------------------------------------------------------------------
extern "C" void kernel_launch(void* const* d_in, const int* in_sizes, int n_in,
                              void* d_out, int out_size) {
    const float* hidden = (const float*)d_in[0];
    const float* amb    = (const float*)d_in[1];
    const float* ta     = (const float*)d_in[2];
    const float* Wself  = (const float*)d_in[3];
    const float* bself  = (const float*)d_in[4];
    const float* Wmerge = (const float*)d_in[5];
    const float* bmerge = (const float*)d_in[6];
    const float* Wtrans = (const float*)d_in[7];
    const float* btrans = (const float*)d_in[8];
    const float* Wl     = (const float*)d_in[9];
    const float* Wr     = (const float*)d_in[10];
    const float* wattn  = (const float*)d_in[11];
    const float* Wd0    = (const float*)d_in[12];
    const float* bd0    = (const float*)d_in[13];
    const float* Wd1    = (const float*)d_in[14];
    const float* bd1    = (const float*)d_in[15];
    const float* Wd2    = (const float*)d_in[16];
    const float* bd2    = (const float*)d_in[17];
    float* out = (float*)d_out;

    kA<<<3, 256>>>(hidden, ta, Wself, bself, Wmerge, bmerge, Wtrans, btrans, Wl, Wr);
    kB<<<NBLK, 256>>>(amb, wattn);
    kC<<<1, 256>>>(Wd0, bd0);
    kD<<<N_AMB, 128>>>(amb, Wd0, Wd1, bd1, Wd2, bd2, out);
}